// round 9
// baseline (speedup 1.0000x reference)
#include <cuda_runtime.h>
#include <cuda_bf16.h>
#include <math_constants.h>

// Dilation2D: out[a,r] = max_{di,db in [-H,H]} input[r+di, a+db] - (di^2+db^2)/(4*scale)
// Separable, block j independent:
//   phase 1: V[y]     = max_di input[clamp(j+di), y] + h(di)   (clamp is provably
//            exact: an OOB row equals a legit smaller-|d| tap with smaller penalty)
//   phase 2: out[a,j] = max_db V[a+db] + h(db)                 (smem, -inf padded)
// 1024 threads = 8 warp-groups; switch(q) makes every tap slice compile-time:
// all d, all -d^2 FFMA immediates, all LDS offsets are literals. 7 instr/tap
// in phase 1 (no predicate/select), 3 instr/tap in phase 2.

#define KK   101
#define HH   (KK / 2)
#define NT   1024
#define NG   8
#define GT   13                  // taps per group (last group: 101-91=10)
#define VPAD 204                 // smem index range: [0, 200]

template<int Q>
__device__ __forceinline__ float p1_taps(const float* __restrict__ col,
                                         int j, float inv) {
    constexpr int lo = -HH + GT * Q;
    constexpr int n  = (Q == NG - 1) ? (KK - GT * (NG - 1)) : GT;
    float a0 = -CUDART_INF_F, a1 = -CUDART_INF_F;
    float a2 = -CUDART_INF_F, a3 = -CUDART_INF_F;
    #pragma unroll
    for (int i = 0; i < n; ++i) {
        constexpr_helper:;
        const int d  = lo + i;                       // compile-time
        const int rc = min(max(j + d, 0), KK - 1);   // clamp only — no select
        const float cand = fmaf((float)(-d * d), inv, __ldg(col + rc * KK));
        if ((i & 3) == 0)      a0 = fmaxf(a0, cand);
        else if ((i & 3) == 1) a1 = fmaxf(a1, cand);
        else if ((i & 3) == 2) a2 = fmaxf(a2, cand);
        else                   a3 = fmaxf(a3, cand);
    }
    return fmaxf(fmaxf(a0, a1), fmaxf(a2, a3));
}

template<int Q>
__device__ __forceinline__ float p2_taps(const float* __restrict__ vb,
                                         float inv) {
    constexpr int lo = -HH + GT * Q;
    constexpr int n  = (Q == NG - 1) ? (KK - GT * (NG - 1)) : GT;
    float a0 = -CUDART_INF_F, a1 = -CUDART_INF_F;
    float a2 = -CUDART_INF_F, a3 = -CUDART_INF_F;
    #pragma unroll
    for (int i = 0; i < n; ++i) {
        const int d = lo + i;                        // compile-time LDS offset
        const float cand = fmaf((float)(-d * d), inv, vb[d]);
        if ((i & 3) == 0)      a0 = fmaxf(a0, cand);
        else if ((i & 3) == 1) a1 = fmaxf(a1, cand);
        else if ((i & 3) == 2) a2 = fmaxf(a2, cand);
        else                   a3 = fmaxf(a3, cand);
    }
    return fmaxf(fmaxf(a0, a1), fmaxf(a2, a3));
}

__global__ __launch_bounds__(NT, 1)
void dil_fused(const float* __restrict__ in,
               const float* __restrict__ scale_p,
               float* __restrict__ out) {
    __shared__ float P[NG][128];        // per-group partials
    __shared__ float V[VPAD];           // -inf padded V row

    const int j  = blockIdx.x;          // V row == output column
    const int t  = threadIdx.x;
    const int q  = t >> 7;              // warp-group 0..7 (uniform per warp)
    const int y  = t & 127;             // lane position 0..127
    const int yc = min(y, KK - 1);      // clamped (all accesses legal)
    const float inv = 1.0f / (4.0f * __ldg(scale_p));

    if (t < VPAD) V[t] = -CUDART_INF_F;

    // ---------- phase 1 ----------
    const float* col = in + yc;
    float v;
    switch (q) {
        case 0: v = p1_taps<0>(col, j, inv); break;
        case 1: v = p1_taps<1>(col, j, inv); break;
        case 2: v = p1_taps<2>(col, j, inv); break;
        case 3: v = p1_taps<3>(col, j, inv); break;
        case 4: v = p1_taps<4>(col, j, inv); break;
        case 5: v = p1_taps<5>(col, j, inv); break;
        case 6: v = p1_taps<6>(col, j, inv); break;
        default: v = p1_taps<7>(col, j, inv); break;
    }
    P[q][y] = v;
    __syncthreads();
    if (q == 0 && y < KK) {
        float m = P[0][y];
        #pragma unroll
        for (int g = 1; g < NG; ++g) m = fmaxf(m, P[g][y]);
        V[HH + y] = m;
    }
    __syncthreads();

    // ---------- phase 2 ----------
    const float* vb = V + HH + yc;      // indices [0,200], all in-bounds
    float w;
    switch (q) {
        case 0: w = p2_taps<0>(vb, inv); break;
        case 1: w = p2_taps<1>(vb, inv); break;
        case 2: w = p2_taps<2>(vb, inv); break;
        case 3: w = p2_taps<3>(vb, inv); break;
        case 4: w = p2_taps<4>(vb, inv); break;
        case 5: w = p2_taps<5>(vb, inv); break;
        case 6: w = p2_taps<6>(vb, inv); break;
        default: w = p2_taps<7>(vb, inv); break;
    }
    __syncthreads();                    // P reuse safe
    P[q][y] = w;
    __syncthreads();
    if (q == 0 && y < KK) {
        float m = P[0][y];
        #pragma unroll
        for (int g = 1; g < NG; ++g) m = fmaxf(m, P[g][y]);
        out[y * KK + j] = m;
    }
}

extern "C" void kernel_launch(void* const* d_in, const int* in_sizes, int n_in,
                              void* d_out, int out_size) {
    const float* in      = (const float*)d_in[0];   // (101,101) float32
    const float* scale_p = (const float*)d_in[1];   // scalar float32
    float*       out     = (float*)d_out;           // (101,101) float32

    dil_fused<<<KK, NT>>>(in, scale_p, out);
}

// round 10
// speedup vs baseline: 1.2605x; 1.2605x over previous
#include <cuda_runtime.h>
#include <cuda_bf16.h>
#include <math_constants.h>

// Dilation2D: out[a,r] = max_{di,db in [-H,H]} input[r+di, a+db] - (di^2+db^2)/(4*scale)
// Separable, block j independent:
//   phase 1: V[y]     = max_di input[clamp(j+di), y] + h(di)
//            (clamp is exact: OOB row == legit smaller-|d| tap with smaller penalty)
//   phase 2: out[a,j] = max_db V[a+db] + h(db)      (smem, -inf padded)
// 512 threads = 4 warp-groups x 26 taps (last: 23); template<Q> makes every
// tap offset / -d^2 immediate a literal. 7 instr/tap p1, 3 instr/tap p2.
// 3 barriers total (separate P2 avoids the reuse barrier).

#define KK   101
#define HH   (KK / 2)
#define NT   512
#define NG   4
#define GT   26                  // groups 0..2: 26 taps, group 3: 23
#define VPAD 204                 // phase-2 index range [0,200]

template<int Q>
__device__ __forceinline__ float p1_taps(const float* __restrict__ col,
                                         int j, float inv) {
    constexpr int lo = -HH + GT * Q;
    constexpr int n  = (Q == NG - 1) ? (KK - GT * (NG - 1)) : GT;
    float a0 = -CUDART_INF_F, a1 = -CUDART_INF_F;
    float a2 = -CUDART_INF_F, a3 = -CUDART_INF_F;
    #pragma unroll
    for (int i = 0; i < n; ++i) {
        const int d  = lo + i;                       // compile-time
        const int rc = min(max(j + d, 0), KK - 1);   // clamp only — no select
        const float cand = fmaf((float)(-d * d), inv, __ldg(col + rc * KK));
        if ((i & 3) == 0)      a0 = fmaxf(a0, cand);
        else if ((i & 3) == 1) a1 = fmaxf(a1, cand);
        else if ((i & 3) == 2) a2 = fmaxf(a2, cand);
        else                   a3 = fmaxf(a3, cand);
    }
    return fmaxf(fmaxf(a0, a1), fmaxf(a2, a3));
}

template<int Q>
__device__ __forceinline__ float p2_taps(const float* __restrict__ vb,
                                         float inv) {
    constexpr int lo = -HH + GT * Q;
    constexpr int n  = (Q == NG - 1) ? (KK - GT * (NG - 1)) : GT;
    float a0 = -CUDART_INF_F, a1 = -CUDART_INF_F;
    float a2 = -CUDART_INF_F, a3 = -CUDART_INF_F;
    #pragma unroll
    for (int i = 0; i < n; ++i) {
        const int d = lo + i;                        // literal LDS offset
        const float cand = fmaf((float)(-d * d), inv, vb[d]);
        if ((i & 3) == 0)      a0 = fmaxf(a0, cand);
        else if ((i & 3) == 1) a1 = fmaxf(a1, cand);
        else if ((i & 3) == 2) a2 = fmaxf(a2, cand);
        else                   a3 = fmaxf(a3, cand);
    }
    return fmaxf(fmaxf(a0, a1), fmaxf(a2, a3));
}

__global__ __launch_bounds__(NT, 1)
void dil_fused(const float* __restrict__ in,
               const float* __restrict__ scale_p,
               float* __restrict__ out) {
    __shared__ float P [NG][128];       // phase-1 partials
    __shared__ float P2[NG][128];       // phase-2 partials (no reuse barrier)
    __shared__ float V[VPAD];           // -inf padded V row

    const int j  = blockIdx.x;          // V row == output column
    const int t  = threadIdx.x;
    const int q  = t >> 7;              // warp-group 0..3 (uniform per warp)
    const int y  = t & 127;             // lane position 0..127
    const int yc = min(y, KK - 1);      // clamped (all accesses legal)
    const float inv = __fdividef(1.0f, 4.0f * __ldg(scale_p));

    if (t < VPAD) V[t] = -CUDART_INF_F;

    // ---------- phase 1 ----------
    const float* col = in + yc;
    float v;
    switch (q) {
        case 0:  v = p1_taps<0>(col, j, inv); break;
        case 1:  v = p1_taps<1>(col, j, inv); break;
        case 2:  v = p1_taps<2>(col, j, inv); break;
        default: v = p1_taps<3>(col, j, inv); break;
    }
    P[q][y] = v;
    __syncthreads();
    if (q == 0 && y < KK)
        V[HH + y] = fmaxf(fmaxf(P[0][y], P[1][y]), fmaxf(P[2][y], P[3][y]));
    __syncthreads();

    // ---------- phase 2 ----------
    const float* vb = V + HH + yc;      // indices [0,200], all in-bounds
    float w;
    switch (q) {
        case 0:  w = p2_taps<0>(vb, inv); break;
        case 1:  w = p2_taps<1>(vb, inv); break;
        case 2:  w = p2_taps<2>(vb, inv); break;
        default: w = p2_taps<3>(vb, inv); break;
    }
    P2[q][y] = w;
    __syncthreads();
    if (q == 0 && y < KK)
        out[y * KK + j] =
            fmaxf(fmaxf(P2[0][y], P2[1][y]), fmaxf(P2[2][y], P2[3][y]));
}

extern "C" void kernel_launch(void* const* d_in, const int* in_sizes, int n_in,
                              void* d_out, int out_size) {
    const float* in      = (const float*)d_in[0];   // (101,101) float32
    const float* scale_p = (const float*)d_in[1];   // scalar float32
    float*       out     = (float*)d_out;           // (101,101) float32

    dil_fused<<<KK, NT>>>(in, scale_p, out);
}

// round 11
// speedup vs baseline: 1.3092x; 1.0386x over previous
#include <cuda_runtime.h>
#include <cuda_bf16.h>
#include <math_constants.h>

// Dilation2D: out[a,r] = max_{di,db in [-H,H]} input[r+di, a+db] - (di^2+db^2)/(4*scale)
// Separable, block j independent:
//   phase 1: V[y]     = max_di input[clamp(j+di), y] + h(di)
//            (clamp is exact: OOB row == legit smaller-|d| tap with smaller penalty)
//   phase 2: out[a,j] = max_db V[a+db] + h(db)      (smem, -inf padded)
// 512 threads = 4 warp-groups x 26 taps; template<Q> makes every tap offset /
// -d^2 immediate a literal. R11: phase-1 loads batched into a register array
// BEFORE any FP math (MLP=26, single L2 exposure); V-init touches pad cells only.

#define KK   101
#define HH   (KK / 2)
#define NT   512
#define NG   4
#define GT   26                  // groups 0..2: 26 taps, group 3: 23
#define VPAD 204                 // phase-2 index range [0,200]

template<int Q>
__device__ __forceinline__ float p1_taps(const float* __restrict__ col,
                                         int j, float inv) {
    constexpr int lo = -HH + GT * Q;
    constexpr int n  = (Q == NG - 1) ? (KK - GT * (NG - 1)) : GT;

    // ---- load batch: all taps in flight before any consumption ----
    float x[n];
    #pragma unroll
    for (int i = 0; i < n; ++i) {
        const int d  = lo + i;                       // compile-time
        const int rc = min(max(j + d, 0), KK - 1);   // clamp only — no select
        x[i] = __ldg(col + rc * KK);
    }
    // ---- compute batch ----
    float a0 = -CUDART_INF_F, a1 = -CUDART_INF_F;
    float a2 = -CUDART_INF_F, a3 = -CUDART_INF_F;
    #pragma unroll
    for (int i = 0; i < n; ++i) {
        const int d = lo + i;
        const float cand = fmaf((float)(-d * d), inv, x[i]);
        if ((i & 3) == 0)      a0 = fmaxf(a0, cand);
        else if ((i & 3) == 1) a1 = fmaxf(a1, cand);
        else if ((i & 3) == 2) a2 = fmaxf(a2, cand);
        else                   a3 = fmaxf(a3, cand);
    }
    return fmaxf(fmaxf(a0, a1), fmaxf(a2, a3));
}

template<int Q>
__device__ __forceinline__ float p2_taps(const float* __restrict__ vb,
                                         float inv) {
    constexpr int lo = -HH + GT * Q;
    constexpr int n  = (Q == NG - 1) ? (KK - GT * (NG - 1)) : GT;
    float a0 = -CUDART_INF_F, a1 = -CUDART_INF_F;
    float a2 = -CUDART_INF_F, a3 = -CUDART_INF_F;
    #pragma unroll
    for (int i = 0; i < n; ++i) {
        const int d = lo + i;                        // literal LDS offset
        const float cand = fmaf((float)(-d * d), inv, vb[d]);
        if ((i & 3) == 0)      a0 = fmaxf(a0, cand);
        else if ((i & 3) == 1) a1 = fmaxf(a1, cand);
        else if ((i & 3) == 2) a2 = fmaxf(a2, cand);
        else                   a3 = fmaxf(a3, cand);
    }
    return fmaxf(fmaxf(a0, a1), fmaxf(a2, a3));
}

__global__ __launch_bounds__(NT, 1)
void dil_fused(const float* __restrict__ in,
               const float* __restrict__ scale_p,
               float* __restrict__ out) {
    __shared__ float P [NG][128];       // phase-1 partials
    __shared__ float P2[NG][128];       // phase-2 partials (no reuse barrier)
    __shared__ float V[VPAD];           // V row, pad cells -inf

    const int j  = blockIdx.x;          // V row == output column
    const int t  = threadIdx.x;
    const int q  = t >> 7;              // warp-group 0..3 (uniform per warp)
    const int y  = t & 127;             // lane position 0..127
    const int yc = min(y, KK - 1);      // clamped (all accesses legal)
    const float inv = __fdividef(1.0f, 4.0f * __ldg(scale_p));

    // pad-only init: cells [0,HH) and [HH+KK, VPAD) — middle is overwritten
    if (t < VPAD && (t < HH || t >= HH + KK)) V[t] = -CUDART_INF_F;

    // ---------- phase 1 ----------
    const float* col = in + yc;
    float v;
    switch (q) {
        case 0:  v = p1_taps<0>(col, j, inv); break;
        case 1:  v = p1_taps<1>(col, j, inv); break;
        case 2:  v = p1_taps<2>(col, j, inv); break;
        default: v = p1_taps<3>(col, j, inv); break;
    }
    P[q][y] = v;
    __syncthreads();
    if (q == 0 && y < KK)
        V[HH + y] = fmaxf(fmaxf(P[0][y], P[1][y]), fmaxf(P[2][y], P[3][y]));
    __syncthreads();

    // ---------- phase 2 ----------
    const float* vb = V + HH + yc;      // indices [0,200], all in-bounds
    float w;
    switch (q) {
        case 0:  w = p2_taps<0>(vb, inv); break;
        case 1:  w = p2_taps<1>(vb, inv); break;
        case 2:  w = p2_taps<2>(vb, inv); break;
        default: w = p2_taps<3>(vb, inv); break;
    }
    P2[q][y] = w;
    __syncthreads();
    if (q == 0 && y < KK)
        out[y * KK + j] =
            fmaxf(fmaxf(P2[0][y], P2[1][y]), fmaxf(P2[2][y], P2[3][y]));
}

extern "C" void kernel_launch(void* const* d_in, const int* in_sizes, int n_in,
                              void* d_out, int out_size) {
    const float* in      = (const float*)d_in[0];   // (101,101) float32
    const float* scale_p = (const float*)d_in[1];   // scalar float32
    float*       out     = (float*)d_out;           // (101,101) float32

    dil_fused<<<KK, NT>>>(in, scale_p, out);
}